// round 5
// baseline (speedup 1.0000x reference)
#include <cuda_runtime.h>
#include <cuda_bf16.h>
#include <cstdint>

// Sparsemax over rows of [B=2048, V=32000] fp32.
// Persistent CTAs (1/SM, 1024 thr), one row at a time held fully in registers
// (8 x float4 per thread). Software-pipelined: next row's loads are issued
// interleaved with current row's stores, so DRAM stays busy across the
// per-row reduce/Michelot bubble.
//   1) exact block max (register FMAX chain + tree reduce)
//   2) compact candidates {x >= rmax - 1.0009} (superset of true support,
//      since tau* >= rmax - 1) via per-thread count + single atomicAdd
//   3) Michelot fixed-point iteration on candidates -> exact tau
//   4) emit max(x - tau, 0) from registers; load next row into same regs

#define THREADS    1024
#define NWARP      32
#define VROW       32000
#define V4ROW      8000
#define PER_THREAD 8
#define CAP        6144
#define NEG_INF    (-3.4e38f)
#define SLACK      1.0009f

__global__ __launch_bounds__(THREADS, 1)
void sparsemax_kernel(const float* __restrict__ in, float* __restrict__ out, int B)
{
    __shared__ float cand[CAP];
    __shared__ float s_red[NWARP];
    __shared__ float s_max;
    __shared__ float s_tau;
    __shared__ int   s_num;

    const int tid  = threadIdx.x;
    const int lane = tid & 31;
    const int wid  = tid >> 5;
    const int G    = gridDim.x;
    const unsigned FULL = 0xffffffffu;

    if (tid == 0) s_num = 0;

    int row = blockIdx.x;
    if (row >= B) return;

    // ---- preload first row ----
    float4 v[PER_THREAD];
    {
        const float4* ir = (const float4*)(in + (size_t)row * VROW);
#pragma unroll
        for (int i = 0; i < PER_THREAD; ++i) {
            int idx = tid + i * THREADS;
            if (i < PER_THREAD - 1 || idx < V4ROW) v[i] = __ldcs(&ir[idx]);
            else v[i] = make_float4(NEG_INF, NEG_INF, NEG_INF, NEG_INF);
        }
    }

    while (row < B) {
        // ---- exact block max ----
        float tm = NEG_INF;
#pragma unroll
        for (int i = 0; i < PER_THREAD; ++i)
            tm = fmaxf(tm, fmaxf(fmaxf(v[i].x, v[i].y), fmaxf(v[i].z, v[i].w)));
#pragma unroll
        for (int o = 16; o; o >>= 1)
            tm = fmaxf(tm, __shfl_xor_sync(FULL, tm, o));
        if (lane == 0) s_red[wid] = tm;
        __syncthreads();
        if (wid == 0) {
            float m = s_red[lane];
#pragma unroll
            for (int o = 16; o; o >>= 1)
                m = fmaxf(m, __shfl_xor_sync(FULL, m, o));
            if (lane == 0) s_max = m;
        }
        __syncthreads();

        const float rmax = s_max;
        const float th = rmax - SLACK;   // tau* >= rmax-1  =>  superset

        // ---- compact candidates (per-thread count, one atomicAdd) ----
        int c = 0;
#pragma unroll
        for (int i = 0; i < PER_THREAD; ++i)
            c += (v[i].x >= th) + (v[i].y >= th) + (v[i].z >= th) + (v[i].w >= th);
        if (c) {
            int base = atomicAdd(&s_num, c);
#pragma unroll
            for (int i = 0; i < PER_THREAD; ++i) {
                float a4[4] = {v[i].x, v[i].y, v[i].z, v[i].w};
#pragma unroll
                for (int e = 0; e < 4; ++e)
                    if (a4[e] >= th) { if (base < CAP) cand[base] = a4[e]; ++base; }
            }
        }
        __syncthreads();

        // ---- Michelot (warp 0): exact tau fixed point ----
        if (wid == 0) {
            const int n = s_num;
            float t = -2.0f;          // shifted domain: candidates-rmax in [-1.0009, 0]
            if (n <= CAP) {
                int prev = -1;
                for (int itc = 0; itc < n + 2; ++itc) {
                    float sum = 0.0f; int cnt = 0;
                    for (int i = lane; i < n; i += 32) {
                        float y = cand[i] - rmax;
                        if (y > t) { sum += y; cnt++; }
                    }
#pragma unroll
                    for (int o = 16; o; o >>= 1) {
                        sum += __shfl_xor_sync(FULL, sum, o);
                        cnt += __shfl_xor_sync(FULL, cnt, o);
                    }
                    if (cnt == prev) break;   // active set stable -> exact tau
                    prev = cnt;
                    t = (sum - 1.0f) / (float)cnt;
                }
            } else {
                // overflow fallback (degenerate inputs only): exact Michelot
                // over the full row from global memory.
                const float* rp = in + (size_t)row * VROW;
                int prev = -1;
                for (int itc = 0; itc < VROW; ++itc) {
                    float sum = 0.0f; int cnt = 0;
                    for (int i = lane; i < VROW; i += 32) {
                        float y = __ldg(&rp[i]) - rmax;
                        if (y > t) { sum += y; cnt++; }
                    }
#pragma unroll
                    for (int o = 16; o; o >>= 1) {
                        sum += __shfl_xor_sync(FULL, sum, o);
                        cnt += __shfl_xor_sync(FULL, cnt, o);
                    }
                    if (cnt == prev) break;
                    prev = cnt;
                    t = (sum - 1.0f) / (float)cnt;
                }
            }
            if (lane == 0) { s_tau = rmax + t; s_num = 0; }  // reset for next row
        }
        __syncthreads();

        const float tau = s_tau;

        // ---- store current row; interleave loads of the next row ----
        const int nrow = row + G;
        const bool more = (nrow < B);
        float4* orow = (float4*)(out + (size_t)row * VROW);
        const float4* nir = (const float4*)(in + (size_t)(more ? nrow : row) * VROW);

#pragma unroll
        for (int i = 0; i < PER_THREAD; ++i) {
            int idx = tid + i * THREADS;
            bool valid = (i < PER_THREAD - 1) || (idx < V4ROW);
            if (valid) {
                float4 r;
                r.x = fmaxf(v[i].x - tau, 0.0f);
                r.y = fmaxf(v[i].y - tau, 0.0f);
                r.z = fmaxf(v[i].z - tau, 0.0f);
                r.w = fmaxf(v[i].w - tau, 0.0f);
                __stcs(&orow[idx], r);
                if (more) v[i] = __ldcs(&nir[idx]);   // prefetch next row
                else      v[i] = make_float4(NEG_INF, NEG_INF, NEG_INF, NEG_INF);
            } else {
                v[i] = make_float4(NEG_INF, NEG_INF, NEG_INF, NEG_INF);
            }
        }
        row = nrow;
    }
}

extern "C" void kernel_launch(void* const* d_in, const int* in_sizes, int n_in,
                              void* d_out, int out_size)
{
    const float* in = (const float*)d_in[0];
    float* out = (float*)d_out;
    const int B = out_size / VROW;

    int sms = 148;
    cudaDeviceGetAttribute(&sms, cudaDevAttrMultiProcessorCount, 0);
    int G = sms;
    if (G > B) G = B;

    sparsemax_kernel<<<G, THREADS>>>(in, out, B);
}

// round 6
// speedup vs baseline: 1.0010x; 1.0010x over previous
#include <cuda_runtime.h>
#include <cuda_bf16.h>
#include <cstdint>

// Sparsemax over rows of [B=2048, V=32000] fp32.
// Persistent CTAs (1/SM, 1024 thr), one row at a time held fully in registers
// (8 x float4 per thread). Software-pipelined: next row's loads are issued
// interleaved with current row's stores, so DRAM stays busy across the
// per-row reduce/Michelot bubble.
//   1) exact block max (register FMAX chain + tree reduce)
//   2) compact candidates {x >= rmax - 1.0009} (superset of true support,
//      since tau* >= rmax - 1) via per-thread count + single atomicAdd
//   3) Michelot fixed-point iteration on candidates -> exact tau
//   4) emit max(x - tau, 0) from registers; load next row into same regs

#define THREADS    1024
#define NWARP      32
#define VROW       32000
#define V4ROW      8000
#define PER_THREAD 8
#define CAP        6144
#define NEG_INF    (-3.4e38f)
#define SLACK      1.0009f

__global__ __launch_bounds__(THREADS, 1)
void sparsemax_kernel(const float* __restrict__ in, float* __restrict__ out, int B)
{
    __shared__ float cand[CAP];
    __shared__ float s_red[NWARP];
    __shared__ float s_max;
    __shared__ float s_tau;
    __shared__ int   s_num;

    const int tid  = threadIdx.x;
    const int lane = tid & 31;
    const int wid  = tid >> 5;
    const int G    = gridDim.x;
    const unsigned FULL = 0xffffffffu;

    if (tid == 0) s_num = 0;

    int row = blockIdx.x;
    if (row >= B) return;

    // ---- preload first row ----
    float4 v[PER_THREAD];
    {
        const float4* ir = (const float4*)(in + (size_t)row * VROW);
#pragma unroll
        for (int i = 0; i < PER_THREAD; ++i) {
            int idx = tid + i * THREADS;
            if (i < PER_THREAD - 1 || idx < V4ROW) v[i] = __ldcs(&ir[idx]);
            else v[i] = make_float4(NEG_INF, NEG_INF, NEG_INF, NEG_INF);
        }
    }

    while (row < B) {
        // ---- exact block max ----
        float tm = NEG_INF;
#pragma unroll
        for (int i = 0; i < PER_THREAD; ++i)
            tm = fmaxf(tm, fmaxf(fmaxf(v[i].x, v[i].y), fmaxf(v[i].z, v[i].w)));
#pragma unroll
        for (int o = 16; o; o >>= 1)
            tm = fmaxf(tm, __shfl_xor_sync(FULL, tm, o));
        if (lane == 0) s_red[wid] = tm;
        __syncthreads();
        if (wid == 0) {
            float m = s_red[lane];
#pragma unroll
            for (int o = 16; o; o >>= 1)
                m = fmaxf(m, __shfl_xor_sync(FULL, m, o));
            if (lane == 0) s_max = m;
        }
        __syncthreads();

        const float rmax = s_max;
        const float th = rmax - SLACK;   // tau* >= rmax-1  =>  superset

        // ---- compact candidates (per-thread count, one atomicAdd) ----
        int c = 0;
#pragma unroll
        for (int i = 0; i < PER_THREAD; ++i)
            c += (v[i].x >= th) + (v[i].y >= th) + (v[i].z >= th) + (v[i].w >= th);
        if (c) {
            int base = atomicAdd(&s_num, c);
#pragma unroll
            for (int i = 0; i < PER_THREAD; ++i) {
                float a4[4] = {v[i].x, v[i].y, v[i].z, v[i].w};
#pragma unroll
                for (int e = 0; e < 4; ++e)
                    if (a4[e] >= th) { if (base < CAP) cand[base] = a4[e]; ++base; }
            }
        }
        __syncthreads();

        // ---- Michelot (warp 0): exact tau fixed point ----
        if (wid == 0) {
            const int n = s_num;
            float t = -2.0f;          // shifted domain: candidates-rmax in [-1.0009, 0]
            if (n <= CAP) {
                int prev = -1;
                for (int itc = 0; itc < n + 2; ++itc) {
                    float sum = 0.0f; int cnt = 0;
                    for (int i = lane; i < n; i += 32) {
                        float y = cand[i] - rmax;
                        if (y > t) { sum += y; cnt++; }
                    }
#pragma unroll
                    for (int o = 16; o; o >>= 1) {
                        sum += __shfl_xor_sync(FULL, sum, o);
                        cnt += __shfl_xor_sync(FULL, cnt, o);
                    }
                    if (cnt == prev) break;   // active set stable -> exact tau
                    prev = cnt;
                    t = (sum - 1.0f) / (float)cnt;
                }
            } else {
                // overflow fallback (degenerate inputs only): exact Michelot
                // over the full row from global memory.
                const float* rp = in + (size_t)row * VROW;
                int prev = -1;
                for (int itc = 0; itc < VROW; ++itc) {
                    float sum = 0.0f; int cnt = 0;
                    for (int i = lane; i < VROW; i += 32) {
                        float y = __ldg(&rp[i]) - rmax;
                        if (y > t) { sum += y; cnt++; }
                    }
#pragma unroll
                    for (int o = 16; o; o >>= 1) {
                        sum += __shfl_xor_sync(FULL, sum, o);
                        cnt += __shfl_xor_sync(FULL, cnt, o);
                    }
                    if (cnt == prev) break;
                    prev = cnt;
                    t = (sum - 1.0f) / (float)cnt;
                }
            }
            if (lane == 0) { s_tau = rmax + t; s_num = 0; }  // reset for next row
        }
        __syncthreads();

        const float tau = s_tau;

        // ---- store current row; interleave loads of the next row ----
        const int nrow = row + G;
        const bool more = (nrow < B);
        float4* orow = (float4*)(out + (size_t)row * VROW);
        const float4* nir = (const float4*)(in + (size_t)(more ? nrow : row) * VROW);

#pragma unroll
        for (int i = 0; i < PER_THREAD; ++i) {
            int idx = tid + i * THREADS;
            bool valid = (i < PER_THREAD - 1) || (idx < V4ROW);
            if (valid) {
                float4 r;
                r.x = fmaxf(v[i].x - tau, 0.0f);
                r.y = fmaxf(v[i].y - tau, 0.0f);
                r.z = fmaxf(v[i].z - tau, 0.0f);
                r.w = fmaxf(v[i].w - tau, 0.0f);
                __stcs(&orow[idx], r);
                if (more) v[i] = __ldcs(&nir[idx]);   // prefetch next row
                else      v[i] = make_float4(NEG_INF, NEG_INF, NEG_INF, NEG_INF);
            } else {
                v[i] = make_float4(NEG_INF, NEG_INF, NEG_INF, NEG_INF);
            }
        }
        row = nrow;
    }
}

extern "C" void kernel_launch(void* const* d_in, const int* in_sizes, int n_in,
                              void* d_out, int out_size)
{
    const float* in = (const float*)d_in[0];
    float* out = (float*)d_out;
    const int B = out_size / VROW;

    int sms = 148;
    cudaDeviceGetAttribute(&sms, cudaDevAttrMultiProcessorCount, 0);
    int G = sms;
    if (G > B) G = B;

    sparsemax_kernel<<<G, THREADS>>>(in, out, B);
}

// round 7
// speedup vs baseline: 1.1782x; 1.1769x over previous
#include <cuda_runtime.h>
#include <cuda_bf16.h>
#include <cstdint>

// Sparsemax over rows of [B=2048, V=32000] fp32.
// Persistent CTAs (1/SM, 1024 thr). Reads are driven by cp.async.bulk (TMA)
// into a 7-slot x 32KB smem ring (1.75 rows of lookahead) so DRAM reads
// stream continuously across all per-row compute/sync bubbles.
// Per row: capture smem->regs (max fused) -> exact block max ->
// candidate superset compaction {x >= rmax-1.0009} -> warp-0 Michelot
// (exact tau) -> register store pass (__stcs) overlapped with next TMA fills.

#define THREADS     1024
#define NWARP       32
#define VROW        32000
#define ROW_F4      8000
#define NCHUNK      4            // chunks per row
#define CHUNK_BYTES 32000
#define CHUNK_F4    2000
#define NSLOT       7            // ring slots (224 KB)
#define CAP         1024
#define NEG_INF     (-3.4e38f)
#define SLACK       1.0009f

// dynamic smem layout (bytes)
#define OFF_BUF    0
#define OFF_CAND   (NSLOT * CHUNK_BYTES)        // 224000
#define OFF_RED    (OFF_CAND + CAP * 4)         // 228096
#define OFF_MISC   (OFF_RED + NWARP * 4)        // 228224: [max, tau, num]
#define OFF_MBAR   (OFF_MISC + 16)              // 228240 (8-aligned)
#define SMEM_TOTAL (OFF_MBAR + NSLOT * 8 + 8)   // 228304

__device__ __forceinline__ uint32_t smem_u32(const void* p) {
    return (uint32_t)__cvta_generic_to_shared(p);
}
__device__ __forceinline__ void mbar_init(uint32_t a, uint32_t cnt) {
    asm volatile("mbarrier.init.shared.b64 [%0], %1;" :: "r"(a), "r"(cnt) : "memory");
}
__device__ __forceinline__ void mbar_expect_tx(uint32_t a, uint32_t tx) {
    asm volatile("mbarrier.arrive.expect_tx.shared.b64 _, [%0], %1;"
                 :: "r"(a), "r"(tx) : "memory");
}
__device__ __forceinline__ void mbar_wait(uint32_t a, uint32_t parity) {
    asm volatile(
        "{\n\t"
        ".reg .pred P1;\n\t"
        "WAIT_LOOP_%=:\n\t"
        "mbarrier.try_wait.parity.acquire.cta.shared::cta.b64 P1, [%0], %1, 0x989680;\n\t"
        "@P1 bra.uni WAIT_DONE_%=;\n\t"
        "bra.uni WAIT_LOOP_%=;\n\t"
        "WAIT_DONE_%=:\n\t"
        "}"
        :: "r"(a), "r"(parity) : "memory");
}
__device__ __forceinline__ void bulk_g2s(uint32_t dst, const void* src,
                                         uint32_t bytes, uint32_t mbar) {
    asm volatile(
        "cp.async.bulk.shared::cta.global.mbarrier::complete_tx::bytes [%0], [%1], %2, [%3];"
        :: "r"(dst), "l"(src), "r"(bytes), "r"(mbar) : "memory");
}
__device__ __forceinline__ void fence_proxy_async() {
    asm volatile("fence.proxy.async;" ::: "memory");
}

__global__ __launch_bounds__(THREADS, 1)
void sparsemax_kernel(const float* __restrict__ in, float* __restrict__ out, int B)
{
    extern __shared__ char smem[];
    float* cand  = (float*)(smem + OFF_CAND);
    float* s_red = (float*)(smem + OFF_RED);
    float* s_max = (float*)(smem + OFF_MISC);
    float* s_tau = (float*)(smem + OFF_MISC + 4);
    int*   s_num = (int*)  (smem + OFF_MISC + 8);
    const uint32_t mb = smem_u32(smem + OFF_MBAR);

    const int tid  = threadIdx.x;
    const int lane = tid & 31;
    const int wid  = tid >> 5;
    const int bid  = blockIdx.x;
    const int G    = gridDim.x;
    const unsigned FULL = 0xffffffffu;

    if (bid >= B) return;

    const int nrows = (B - bid + G - 1) / G;
    const int Q = NCHUNK * nrows;          // total chunks for this CTA

    if (tid == 0) {
        *s_num = 0;
        for (int s = 0; s < NSLOT; ++s) mbar_init(mb + s * 8, 1);
        fence_proxy_async();
    }
    __syncthreads();

    // ---- prime the ring: issue first min(NSLOT, Q) chunk loads ----
    int qi = 0;   // issue counter (only meaningful on tid 0)
    if (tid == 0) {
        int lim = Q < NSLOT ? Q : NSLOT;
        for (; qi < lim; ++qi) {
            int lr = qi >> 2, ck = qi & 3;
            const char* src = (const char*)(in + (size_t)(bid + lr * G) * VROW)
                              + (size_t)ck * CHUNK_BYTES;
            uint32_t m = mb + (qi % NSLOT) * 8;
            mbar_expect_tx(m, CHUNK_BYTES);
            bulk_g2s(smem_u32(smem + OFF_BUF + (qi % NSLOT) * CHUNK_BYTES),
                     src, CHUNK_BYTES, m);
        }
    }

    for (int lr = 0; lr < nrows; ++lr) {
        const int row = bid + lr * G;
        const int qbase = lr * NCHUNK;

        // ---- capture row smem -> registers, fused max scan ----
        float4 v[8];
        float tm = NEG_INF;
#pragma unroll
        for (int k = 0; k < NCHUNK; ++k) {
            const int q = qbase + k;
            const int slot = q % NSLOT;
            mbar_wait(mb + slot * 8, (q / NSLOT) & 1);
            const float4* cb = (const float4*)(smem + OFF_BUF + slot * CHUNK_BYTES);
            v[2 * k] = cb[tid];
            tm = fmaxf(tm, fmaxf(fmaxf(v[2*k].x, v[2*k].y), fmaxf(v[2*k].z, v[2*k].w)));
            if (tid < CHUNK_F4 - THREADS) {              // tid < 976
                v[2 * k + 1] = cb[tid + THREADS];
                tm = fmaxf(tm, fmaxf(fmaxf(v[2*k+1].x, v[2*k+1].y),
                                     fmaxf(v[2*k+1].z, v[2*k+1].w)));
            } else {
                v[2 * k + 1] = make_float4(NEG_INF, NEG_INF, NEG_INF, NEG_INF);
            }
        }

        // ---- exact block max ----
#pragma unroll
        for (int o = 16; o; o >>= 1)
            tm = fmaxf(tm, __shfl_xor_sync(FULL, tm, o));
        if (lane == 0) s_red[wid] = tm;
        __syncthreads();          // all captures of this row complete here
        if (wid == 0) {
            float m = s_red[lane];
#pragma unroll
            for (int o = 16; o; o >>= 1)
                m = fmaxf(m, __shfl_xor_sync(FULL, m, o));
            if (lane == 0) {
                *s_max = m;
                // ---- refill ring: this row's 4 slots are now free ----
                int lim = qi + NCHUNK; if (lim > Q) lim = Q;
                for (; qi < lim; ++qi) {
                    int ilr = qi >> 2, ck = qi & 3;
                    const char* src = (const char*)(in + (size_t)(bid + ilr * G) * VROW)
                                      + (size_t)ck * CHUNK_BYTES;
                    uint32_t mm = mb + (qi % NSLOT) * 8;
                    mbar_expect_tx(mm, CHUNK_BYTES);
                    bulk_g2s(smem_u32(smem + OFF_BUF + (qi % NSLOT) * CHUNK_BYTES),
                             src, CHUNK_BYTES, mm);
                }
            }
        }
        __syncthreads();

        const float rmax = *s_max;
        const float th = rmax - SLACK;   // tau* >= rmax-1 => superset condition

        // ---- compact candidates (per-thread count, one atomicAdd) ----
        int c = 0;
#pragma unroll
        for (int i = 0; i < 8; ++i)
            c += (v[i].x >= th) + (v[i].y >= th) + (v[i].z >= th) + (v[i].w >= th);
        if (c) {
            int base = atomicAdd(s_num, c);
#pragma unroll
            for (int i = 0; i < 8; ++i) {
                float a4[4] = {v[i].x, v[i].y, v[i].z, v[i].w};
#pragma unroll
                for (int e = 0; e < 4; ++e)
                    if (a4[e] >= th) { if (base < CAP) cand[base] = a4[e]; ++base; }
            }
        }
        __syncthreads();

        // ---- Michelot (warp 0): exact tau fixed point ----
        if (wid == 0) {
            const int n = *s_num;
            float t = -2.0f;
            if (n <= CAP) {
                int prev = -1;
                for (int itc = 0; itc < n + 2; ++itc) {
                    float sum = 0.0f; int cnt = 0;
                    for (int i = lane; i < n; i += 32) {
                        float y = cand[i] - rmax;
                        if (y > t) { sum += y; cnt++; }
                    }
#pragma unroll
                    for (int o = 16; o; o >>= 1) {
                        sum += __shfl_xor_sync(FULL, sum, o);
                        cnt += __shfl_xor_sync(FULL, cnt, o);
                    }
                    if (cnt == prev) break;   // fixed point -> exact tau
                    prev = cnt;
                    t = (sum - 1.0f) / (float)cnt;
                }
            } else {
                // overflow fallback (degenerate inputs only): exact Michelot
                // over the full row from global memory.
                const float* rp = in + (size_t)row * VROW;
                int prev = -1;
                for (int itc = 0; itc < VROW; ++itc) {
                    float sum = 0.0f; int cnt = 0;
                    for (int i = lane; i < VROW; i += 32) {
                        float y = __ldg(&rp[i]) - rmax;
                        if (y > t) { sum += y; cnt++; }
                    }
#pragma unroll
                    for (int o = 16; o; o >>= 1) {
                        sum += __shfl_xor_sync(FULL, sum, o);
                        cnt += __shfl_xor_sync(FULL, cnt, o);
                    }
                    if (cnt == prev) break;
                    prev = cnt;
                    t = (sum - 1.0f) / (float)cnt;
                }
            }
            if (lane == 0) { *s_tau = rmax + t; *s_num = 0; }
        }
        __syncthreads();

        const float tau = *s_tau;

        // ---- store row from registers (TMA keeps filling behind this) ----
        float4* orow = (float4*)(out + (size_t)row * VROW);
#pragma unroll
        for (int k = 0; k < NCHUNK; ++k) {
            int idx = k * CHUNK_F4 + tid;
            float4 r;
            r.x = fmaxf(v[2*k].x - tau, 0.0f);
            r.y = fmaxf(v[2*k].y - tau, 0.0f);
            r.z = fmaxf(v[2*k].z - tau, 0.0f);
            r.w = fmaxf(v[2*k].w - tau, 0.0f);
            __stcs(&orow[idx], r);
            if (tid < CHUNK_F4 - THREADS) {
                float4 r2;
                r2.x = fmaxf(v[2*k+1].x - tau, 0.0f);
                r2.y = fmaxf(v[2*k+1].y - tau, 0.0f);
                r2.z = fmaxf(v[2*k+1].z - tau, 0.0f);
                r2.w = fmaxf(v[2*k+1].w - tau, 0.0f);
                __stcs(&orow[idx + THREADS], r2);
            }
        }
    }
}

extern "C" void kernel_launch(void* const* d_in, const int* in_sizes, int n_in,
                              void* d_out, int out_size)
{
    const float* in = (const float*)d_in[0];
    float* out = (float*)d_out;
    const int B = out_size / VROW;

    int sms = 148;
    cudaDeviceGetAttribute(&sms, cudaDevAttrMultiProcessorCount, 0);
    int G = sms;
    if (G > B) G = B;

    cudaFuncSetAttribute(sparsemax_kernel,
                         cudaFuncAttributeMaxDynamicSharedMemorySize, SMEM_TOTAL);
    sparsemax_kernel<<<G, THREADS, SMEM_TOTAL>>>(in, out, B);
}

// round 8
// speedup vs baseline: 1.2010x; 1.0194x over previous
#include <cuda_runtime.h>
#include <cuda_bf16.h>
#include <cstdint>

// Sparsemax over rows of [B=2048, V=32000] fp32.
// Persistent CTAs (1/SM, 1024 thr). cp.async.bulk (TMA) drives reads into a
// 7-slot x 32KB smem ring. Per row:
//   capture smem->regs (max fused) -> block max via atomicMax(monotone key)
//   -> candidate superset {x >= rmax-1.0009} compaction (count+atomicAdd)
//   -> Michelot fixed point run REDUNDANTLY by every warp (no barrier after)
//   -> register store pass (__stcs), overlapped with next row's TMA fills.
// Candidate state double-buffered by row parity: only 2 __syncthreads/row.

#define THREADS     1024
#define VROW        32000
#define NCHUNK      4
#define CHUNK_BYTES 32000
#define CHUNK_F4    2000
#define NSLOT       7
#define CAP         512
#define NEG_INF     (-3.4e38f)
#define SLACK       1.0009f

// dynamic smem layout (bytes)
#define OFF_BUF    0
#define OFF_CAND   (NSLOT * CHUNK_BYTES)          // 224000
#define OFF_NUM    (OFF_CAND + 2 * CAP * 4)       // 228096
#define OFF_MAXB   (OFF_NUM + 8)                  // 228104
#define OFF_MBAR   (OFF_MAXB + 8)                 // 228112 (8-aligned)
#define SMEM_TOTAL (OFF_MBAR + NSLOT * 8)         // 228168

__device__ __forceinline__ uint32_t smem_u32(const void* p) {
    return (uint32_t)__cvta_generic_to_shared(p);
}
__device__ __forceinline__ void mbar_init(uint32_t a, uint32_t cnt) {
    asm volatile("mbarrier.init.shared.b64 [%0], %1;" :: "r"(a), "r"(cnt) : "memory");
}
__device__ __forceinline__ void mbar_expect_tx(uint32_t a, uint32_t tx) {
    asm volatile("mbarrier.arrive.expect_tx.shared.b64 _, [%0], %1;"
                 :: "r"(a), "r"(tx) : "memory");
}
__device__ __forceinline__ void mbar_wait(uint32_t a, uint32_t parity) {
    asm volatile(
        "{\n\t"
        ".reg .pred P1;\n\t"
        "WAIT_LOOP_%=:\n\t"
        "mbarrier.try_wait.parity.acquire.cta.shared::cta.b64 P1, [%0], %1, 0x989680;\n\t"
        "@P1 bra.uni WAIT_DONE_%=;\n\t"
        "bra.uni WAIT_LOOP_%=;\n\t"
        "WAIT_DONE_%=:\n\t"
        "}"
        :: "r"(a), "r"(parity) : "memory");
}
__device__ __forceinline__ void bulk_g2s(uint32_t dst, const void* src,
                                         uint32_t bytes, uint32_t mbar) {
    asm volatile(
        "cp.async.bulk.shared::cta.global.mbarrier::complete_tx::bytes [%0], [%1], %2, [%3];"
        :: "r"(dst), "l"(src), "r"(bytes), "r"(mbar) : "memory");
}
__device__ __forceinline__ void fence_proxy_async() {
    asm volatile("fence.proxy.async;" ::: "memory");
}

// monotone float<->uint key: order-preserving for all finite floats
__device__ __forceinline__ unsigned fkey(float x) {
    unsigned u = __float_as_uint(x);
    return (u & 0x80000000u) ? ~u : (u | 0x80000000u);
}
__device__ __forceinline__ float funkey(unsigned k) {
    unsigned u = (k & 0x80000000u) ? (k ^ 0x80000000u) : ~k;
    return __uint_as_float(u);
}

__global__ __launch_bounds__(THREADS, 1)
void sparsemax_kernel(const float* __restrict__ in, float* __restrict__ out, int B)
{
    extern __shared__ char smem[];
    float*    cand   = (float*)(smem + OFF_CAND);       // [2][CAP]
    int*      s_num  = (int*)(smem + OFF_NUM);          // [2]
    unsigned* s_maxb = (unsigned*)(smem + OFF_MAXB);    // [2]
    const uint32_t mb = smem_u32(smem + OFF_MBAR);

    const int tid  = threadIdx.x;
    const int lane = tid & 31;
    const int bid  = blockIdx.x;
    const int G    = gridDim.x;
    const unsigned FULL = 0xffffffffu;

    if (bid >= B) return;

    const int nrows = (B - bid + G - 1) / G;
    const int Q = NCHUNK * nrows;

    if (tid == 0) {
        s_num[0] = 0;  s_num[1] = 0;
        s_maxb[0] = 0; s_maxb[1] = 0;
        for (int s = 0; s < NSLOT; ++s) mbar_init(mb + s * 8, 1);
        fence_proxy_async();
    }
    __syncthreads();

    // ---- prime the ring ----
    int qi = 0;
    if (tid == 0) {
        int lim = Q < NSLOT ? Q : NSLOT;
        for (; qi < lim; ++qi) {
            int lr2 = qi >> 2, ck = qi & 3;
            const char* src = (const char*)(in + (size_t)(bid + lr2 * G) * VROW)
                              + (size_t)ck * CHUNK_BYTES;
            uint32_t m = mb + (qi % NSLOT) * 8;
            mbar_expect_tx(m, CHUNK_BYTES);
            bulk_g2s(smem_u32(smem + OFF_BUF + (qi % NSLOT) * CHUNK_BYTES),
                     src, CHUNK_BYTES, m);
        }
    }

    for (int lr = 0; lr < nrows; ++lr) {
        const int row = bid + lr * G;
        const int p   = lr & 1;                 // parity buffer for this row
        float*    cbuf = cand + p * CAP;

        // ---- capture row smem -> regs, fused max scan ----
        float4 v[8];
        float tm = NEG_INF;
#pragma unroll
        for (int k = 0; k < NCHUNK; ++k) {
            const int q = lr * NCHUNK + k;
            const int slot = q % NSLOT;
            mbar_wait(mb + slot * 8, (q / NSLOT) & 1);
            const float4* cb = (const float4*)(smem + OFF_BUF + slot * CHUNK_BYTES);
            v[2 * k] = cb[tid];
            tm = fmaxf(tm, fmaxf(fmaxf(v[2*k].x, v[2*k].y), fmaxf(v[2*k].z, v[2*k].w)));
            if (tid < CHUNK_F4 - THREADS) {     // tid < 976
                v[2 * k + 1] = cb[tid + THREADS];
                tm = fmaxf(tm, fmaxf(fmaxf(v[2*k+1].x, v[2*k+1].y),
                                     fmaxf(v[2*k+1].z, v[2*k+1].w)));
            } else {
                v[2 * k + 1] = make_float4(NEG_INF, NEG_INF, NEG_INF, NEG_INF);
            }
        }

        // ---- block max: warp reduce + one atomicMax per warp ----
#pragma unroll
        for (int o = 16; o; o >>= 1)
            tm = fmaxf(tm, __shfl_xor_sync(FULL, tm, o));
        if (lane == 0) atomicMax(&s_maxb[p], fkey(tm));
        __syncthreads();                         // sync A: max done, captures done

        const float rmax = funkey(s_maxb[p]);
        const float th = rmax - SLACK;           // tau* >= rmax-1 => superset

        // tid0: reset other-parity state for the NEXT row, then refill ring
        if (tid == 0) {
            s_num[p ^ 1] = 0;
            s_maxb[p ^ 1] = 0;
            int lim = qi + NCHUNK; if (lim > Q) lim = Q;
            for (; qi < lim; ++qi) {
                int ilr = qi >> 2, ck = qi & 3;
                const char* src = (const char*)(in + (size_t)(bid + ilr * G) * VROW)
                                  + (size_t)ck * CHUNK_BYTES;
                uint32_t mm = mb + (qi % NSLOT) * 8;
                mbar_expect_tx(mm, CHUNK_BYTES);
                bulk_g2s(smem_u32(smem + OFF_BUF + (qi % NSLOT) * CHUNK_BYTES),
                         src, CHUNK_BYTES, mm);
            }
        }

        // ---- compact candidates (per-thread count, one atomicAdd) ----
        int c = 0;
#pragma unroll
        for (int i = 0; i < 8; ++i)
            c += (v[i].x >= th) + (v[i].y >= th) + (v[i].z >= th) + (v[i].w >= th);
        if (c) {
            int base = atomicAdd(&s_num[p], c);
#pragma unroll
            for (int i = 0; i < 8; ++i) {
                float a4[4] = {v[i].x, v[i].y, v[i].z, v[i].w};
#pragma unroll
                for (int e = 0; e < 4; ++e)
                    if (a4[e] >= th) { if (base < CAP) cbuf[base] = a4[e]; ++base; }
            }
        }
        __syncthreads();                         // sync B: candidates complete

        // ---- Michelot, redundantly in EVERY warp (no barrier after) ----
        const int n = s_num[p];
        float t = -2.0f;
        if (n <= CAP) {
            int prev = -1;
            for (int itc = 0; itc < n + 2; ++itc) {
                float sum = 0.0f; int cnt = 0;
                for (int i = lane; i < n; i += 32) {
                    float y = cbuf[i] - rmax;
                    if (y > t) { sum += y; cnt++; }
                }
#pragma unroll
                for (int o = 16; o; o >>= 1) {
                    sum += __shfl_xor_sync(FULL, sum, o);
                    cnt += __shfl_xor_sync(FULL, cnt, o);
                }
                if (cnt == prev) break;          // fixed point -> exact tau
                prev = cnt;
                t = (sum - 1.0f) / (float)cnt;
            }
        } else {
            // overflow fallback (degenerate inputs only): exact Michelot over
            // the full row from global memory, redundantly per warp.
            const float* rp = in + (size_t)row * VROW;
            int prev = -1;
            for (int itc = 0; itc < VROW; ++itc) {
                float sum = 0.0f; int cnt = 0;
                for (int i = lane; i < VROW; i += 32) {
                    float y = __ldg(&rp[i]) - rmax;
                    if (y > t) { sum += y; cnt++; }
                }
#pragma unroll
                for (int o = 16; o; o >>= 1) {
                    sum += __shfl_xor_sync(FULL, sum, o);
                    cnt += __shfl_xor_sync(FULL, cnt, o);
                }
                if (cnt == prev) break;
                prev = cnt;
                t = (sum - 1.0f) / (float)cnt;
            }
        }
        const float tau = rmax + t;

        // ---- store row from registers (TMA keeps filling behind this) ----
        float4* orow = (float4*)(out + (size_t)row * VROW);
#pragma unroll
        for (int k = 0; k < NCHUNK; ++k) {
            int idx = k * CHUNK_F4 + tid;
            float4 r;
            r.x = fmaxf(v[2*k].x - tau, 0.0f);
            r.y = fmaxf(v[2*k].y - tau, 0.0f);
            r.z = fmaxf(v[2*k].z - tau, 0.0f);
            r.w = fmaxf(v[2*k].w - tau, 0.0f);
            __stcs(&orow[idx], r);
            if (tid < CHUNK_F4 - THREADS) {
                float4 r2;
                r2.x = fmaxf(v[2*k+1].x - tau, 0.0f);
                r2.y = fmaxf(v[2*k+1].y - tau, 0.0f);
                r2.z = fmaxf(v[2*k+1].z - tau, 0.0f);
                r2.w = fmaxf(v[2*k+1].w - tau, 0.0f);
                __stcs(&orow[idx + THREADS], r2);
            }
        }
    }
}

extern "C" void kernel_launch(void* const* d_in, const int* in_sizes, int n_in,
                              void* d_out, int out_size)
{
    const float* in = (const float*)d_in[0];
    float* out = (float*)d_out;
    const int B = out_size / VROW;

    int sms = 148;
    cudaDeviceGetAttribute(&sms, cudaDevAttrMultiProcessorCount, 0);
    int G = sms;
    if (G > B) G = B;

    cudaFuncSetAttribute(sparsemax_kernel,
                         cudaFuncAttributeMaxDynamicSharedMemorySize, SMEM_TOTAL);
    sparsemax_kernel<<<G, THREADS, SMEM_TOTAL>>>(in, out, B);
}